// round 2
// baseline (speedup 1.0000x reference)
#include <cuda_runtime.h>

// Problem constants (fixed shapes)
#define NN 50000
#define EE 1600000
#define DD 128
#define CC 10
#define LL 4
#define GG 512
#define NBLK 391            // ceil(NN/128)
#define BN_EPS 1e-5f

// ---------------- scratch (device globals; no allocations) ----------------
__device__ float g_h[NN * DD];        // current node features
__device__ float g_z[NN * DD];        // ping
__device__ float g_y[NN * DD];        // pong
__device__ int   g_rowptr[NN + 1];
__device__ int   g_off[NN];           // counts -> row starts -> fill cursors
__device__ int   g_col[EE];
__device__ int   g_gstart[GG + 1];
__device__ float g_part[NBLK * 2 * DD];   // per-block BN partials (sum, sumsq)
__device__ float g_scale[DD];
__device__ float g_shift[DD];
__device__ float g_logits[GG * CC];

// ---------------- CSR build ----------------
__global__ void k_zero_off() {
    int i = blockIdx.x * blockDim.x + threadIdx.x;
    if (i < NN) g_off[i] = 0;
}

__global__ void k_hist(const int* __restrict__ dst) {
    int e = blockIdx.x * blockDim.x + threadIdx.x;
    if (e < EE) atomicAdd(&g_off[dst[e]], 1);
}

// single-block exclusive scan of counts -> rowptr; also leaves row starts in g_off
__global__ void k_scan() {
    __shared__ int buf[1024];
    __shared__ int carry_s;
    int t = threadIdx.x;
    if (t == 0) { carry_s = 0; g_rowptr[0] = 0; }
    __syncthreads();
    for (int base = 0; base < NN; base += 1024) {
        int i = base + t;
        int v = (i < NN) ? g_off[i] : 0;
        buf[t] = v;
        __syncthreads();
        for (int ofs = 1; ofs < 1024; ofs <<= 1) {
            int add = (t >= ofs) ? buf[t - ofs] : 0;
            __syncthreads();
            buf[t] += add;
            __syncthreads();
        }
        int inc = buf[t] + carry_s;
        if (i < NN) { g_rowptr[i + 1] = inc; g_off[i] = inc - v; }
        __syncthreads();
        if (t == 1023) carry_s = inc;
        __syncthreads();
    }
}

__global__ void k_fill(const int* __restrict__ src, const int* __restrict__ dst) {
    int e = blockIdx.x * blockDim.x + threadIdx.x;
    if (e < EE) {
        int p = atomicAdd(&g_off[dst[e]], 1);
        g_col[p] = src[e];
    }
}

// graph boundaries by binary search (batch is sorted)
__global__ void k_gstart(const int* __restrict__ batch) {
    int g = threadIdx.x;  // 512 threads
    int lo = 0, hi = NN;
    while (lo < hi) {
        int mid = (lo + hi) >> 1;
        if (batch[mid] < g) lo = mid + 1; else hi = mid;
    }
    g_gstart[g] = lo;
    if (g == 0) g_gstart[GG] = NN;
}

// ---------------- neighbor gather: z = h + sum_{e: dst==n} h[src] ----------------
__global__ void k_gather() {
    int gw   = (blockIdx.x * blockDim.x + threadIdx.x) >> 5;  // node = global warp
    int lane = threadIdx.x & 31;
    if (gw >= NN) return;
    const float4* hv = (const float4*)g_h;
    float4 acc = hv[gw * 32 + lane];
    int i = g_rowptr[gw];
    int e = g_rowptr[gw + 1];
    for (; i + 4 <= e; i += 4) {
        int n0 = g_col[i], n1 = g_col[i + 1], n2 = g_col[i + 2], n3 = g_col[i + 3];
        float4 v0 = hv[n0 * 32 + lane];
        float4 v1 = hv[n1 * 32 + lane];
        float4 v2 = hv[n2 * 32 + lane];
        float4 v3 = hv[n3 * 32 + lane];
        acc.x += (v0.x + v1.x) + (v2.x + v3.x);
        acc.y += (v0.y + v1.y) + (v2.y + v3.y);
        acc.z += (v0.z + v1.z) + (v2.z + v3.z);
        acc.w += (v0.w + v1.w) + (v2.w + v3.w);
    }
    for (; i < e; i++) {
        int n0 = g_col[i];
        float4 v = hv[n0 * 32 + lane];
        acc.x += v.x; acc.y += v.y; acc.z += v.z; acc.w += v.w;
    }
    ((float4*)g_z)[gw * 32 + lane] = acc;
}

// ---------------- GEMM: C = act(A) @ W + bias, with fused BN-stats epilogue -------
// FUSE=false: A = g_z (raw), C = g_y
// FUSE=true : A = relu(g_y * g_scale + g_shift), C = g_z
#define GEMM_SMEM ((128 * 129 + 128 * 128 + 256) * 4)

template <bool FUSE>
__global__ __launch_bounds__(256, 1) void k_gemm(const float* __restrict__ W,
                                                 const float* __restrict__ bias) {
    extern __shared__ float sm[];
    float* As   = sm;                    // [128][129]
    float* Bs   = sm + 128 * 129;        // [128][128], k-major (matches W layout)
    float* Sred = Bs + 128 * 128;        // [256]: colsum, colsumsq

    const float* A  = FUSE ? g_y : g_z;
    float*       Cm = FUSE ? g_z : g_y;

    int tid = threadIdx.x;
    int m0  = blockIdx.x << 7;

    Sred[tid] = 0.0f;

    // load W tile (k-major already)
    {
        const float4* Wv = (const float4*)W;
        float4* Bv = (float4*)Bs;
#pragma unroll
        for (int i = 0; i < 16; i++) Bv[i * 256 + tid] = Wv[i * 256 + tid];
    }
    // load A tile (row-major, padded rows zero), optionally fused BN+ReLU
    {
        const float4* Av = (const float4*)A;
#pragma unroll
        for (int i = 0; i < 16; i++) {
            int idx = i * 256 + tid;
            int row = idx >> 5, c4 = idx & 31;
            int gm  = m0 + row;
            float4 v = make_float4(0.f, 0.f, 0.f, 0.f);
            if (gm < NN) {
                v = Av[gm * 32 + c4];
                if (FUSE) {
                    int k = c4 << 2;
                    v.x = fmaxf(fmaf(v.x, g_scale[k + 0], g_shift[k + 0]), 0.f);
                    v.y = fmaxf(fmaf(v.y, g_scale[k + 1], g_shift[k + 1]), 0.f);
                    v.z = fmaxf(fmaf(v.z, g_scale[k + 2], g_shift[k + 2]), 0.f);
                    v.w = fmaxf(fmaf(v.w, g_scale[k + 3], g_shift[k + 3]), 0.f);
                }
            }
            float* d = As + row * 129 + (c4 << 2);
            d[0] = v.x; d[1] = v.y; d[2] = v.z; d[3] = v.w;
        }
    }
    __syncthreads();

    int tx = tid & 15, ty = tid >> 4;
    // 8 rows x 8 cols per thread, cols packed in f32x2 pairs
    unsigned long long acc[8][4];
#pragma unroll
    for (int i = 0; i < 8; i++)
#pragma unroll
        for (int j = 0; j < 4; j++) acc[i][j] = 0ull;

    const float* arow = As + (ty * 8) * 129;
    const float* bcol = Bs + tx * 8;

#pragma unroll 4
    for (int k = 0; k < 128; k++) {
        unsigned long long b2[4];
#pragma unroll
        for (int j = 0; j < 4; j++)
            b2[j] = *(const unsigned long long*)(bcol + k * 128 + 2 * j);
#pragma unroll
        for (int i = 0; i < 8; i++) {
            unsigned au = __float_as_uint(arow[i * 129 + k]);
            unsigned long long a2;
            asm("mov.b64 %0, {%1, %1};" : "=l"(a2) : "r"(au));
#pragma unroll
            for (int j = 0; j < 4; j++)
                asm("fma.rn.f32x2 %0, %1, %2, %0;" : "+l"(acc[i][j]) : "l"(a2), "l"(b2[j]));
        }
    }

    // epilogue: bias, store, per-block BN partials (valid rows only)
    float csum[8], csq[8];
#pragma unroll
    for (int j = 0; j < 8; j++) { csum[j] = 0.f; csq[j] = 0.f; }
#pragma unroll
    for (int i = 0; i < 8; i++) {
        int gm = m0 + ty * 8 + i;
        if (gm < NN) {
            float2* crow = (float2*)(Cm + gm * 128);
#pragma unroll
            for (int j = 0; j < 4; j++) {
                float vx = __uint_as_float((unsigned)(acc[i][j] & 0xffffffffull));
                float vy = __uint_as_float((unsigned)(acc[i][j] >> 32));
                int c0 = tx * 8 + 2 * j;
                vx += bias[c0]; vy += bias[c0 + 1];
                crow[c0 >> 1] = make_float2(vx, vy);
                csum[2 * j]     += vx; csq[2 * j]     += vx * vx;
                csum[2 * j + 1] += vy; csq[2 * j + 1] += vy * vy;
            }
        }
    }
#pragma unroll
    for (int j = 0; j < 8; j++) {
        int c = tx * 8 + j;
        atomicAdd(&Sred[c], csum[j]);
        atomicAdd(&Sred[128 + c], csq[j]);
    }
    __syncthreads();
    if (tid < 128) {
        g_part[blockIdx.x * 256 + tid]       = Sred[tid];
        g_part[blockIdx.x * 256 + 128 + tid] = Sred[128 + tid];
    }
}

// ---------------- BN stats reduce -> scale/shift ----------------
__global__ void k_stats(const float* __restrict__ gamma, const float* __restrict__ beta) {
    int d = threadIdx.x;  // 128
    float s = 0.f, q = 0.f;
    for (int b = 0; b < NBLK; b++) {
        s += g_part[b * 256 + d];
        q += g_part[b * 256 + 128 + d];
    }
    float m = s * (1.0f / NN);
    float v = fmaxf(q * (1.0f / NN) - m * m, 0.f);
    float istd = rsqrtf(v + BN_EPS);
    float sc = istd * gamma[d];
    g_scale[d] = sc;
    g_shift[d] = beta[d] - m * sc;
}

// ---------------- normalize(+relu) + write h + pool + head ----------------
// NORM=false: src = xsrc (raw input, also copies x into g_h), first scale (init=1)
// NORM=true : src = g_z normalized via g_scale/g_shift + relu -> g_h
template <bool NORM>
__global__ void k_pool(const float* __restrict__ xsrc, const float* __restrict__ fcW,
                       const float* __restrict__ fcb, int init) {
    __shared__ float pooled[DD];
    int g = blockIdx.x, d = threadIdx.x;  // 512 blocks x 128 threads
    const float* src = NORM ? g_z : xsrc;
    int s = g_gstart[g], e = g_gstart[g + 1];
    float sc = 0.f, sh = 0.f;
    if (NORM) { sc = g_scale[d]; sh = g_shift[d]; }
    float acc = 0.f;
    for (int n = s; n < e; n++) {
        float v = src[n * DD + d];
        if (NORM) v = fmaxf(fmaf(v, sc, sh), 0.f);
        g_h[n * DD + d] = v;
        acc += v;
    }
    pooled[d] = acc;
    __syncthreads();
    if (d < CC) {
        float lg = fcb[d];
#pragma unroll 8
        for (int k = 0; k < DD; k++) lg += pooled[k] * fcW[k * CC + d];
        if (init) g_logits[g * CC + d] = lg;
        else      g_logits[g * CC + d] += lg;
    }
}

// ---------------- log_softmax ----------------
__global__ void k_softmax(float* __restrict__ out) {
    int g = blockIdx.x * blockDim.x + threadIdx.x;
    if (g >= GG) return;
    float v[CC], mx = -1e30f;
#pragma unroll
    for (int c = 0; c < CC; c++) { v[c] = g_logits[g * CC + c]; mx = fmaxf(mx, v[c]); }
    float ssum = 0.f;
#pragma unroll
    for (int c = 0; c < CC; c++) ssum += expf(v[c] - mx);
    float lse = mx + logf(ssum);
#pragma unroll
    for (int c = 0; c < CC; c++) out[g * CC + c] = v[c] - lse;
}

// ---------------- launch ----------------
extern "C" void kernel_launch(void* const* d_in, const int* in_sizes, int n_in,
                              void* d_out, int out_size) {
    const float* x     = (const float*)d_in[0];
    const int*   ei    = (const int*)d_in[1];
    const int*   batch = (const int*)d_in[2];
    // d_in[3] = num_graphs (compile-time GG)
    const float* cW1  = (const float*)d_in[4];
    const float* cb1  = (const float*)d_in[5];
    const float* cbng = (const float*)d_in[6];
    const float* cbnb = (const float*)d_in[7];
    const float* cW2  = (const float*)d_in[8];
    const float* cb2  = (const float*)d_in[9];
    const float* bng  = (const float*)d_in[10];
    const float* bnb  = (const float*)d_in[11];
    const float* fcW  = (const float*)d_in[12];
    const float* fcb  = (const float*)d_in[13];
    float* out = (float*)d_out;

    cudaFuncSetAttribute(k_gemm<false>, cudaFuncAttributeMaxDynamicSharedMemorySize, GEMM_SMEM);
    cudaFuncSetAttribute(k_gemm<true>,  cudaFuncAttributeMaxDynamicSharedMemorySize, GEMM_SMEM);

    const int* srcI = ei;
    const int* dstI = ei + EE;

    // CSR + graph boundaries
    k_zero_off<<<(NN + 255) / 256, 256>>>();
    k_hist<<<(EE + 255) / 256, 256>>>(dstI);
    k_scan<<<1, 1024>>>();
    k_fill<<<(EE + 255) / 256, 256>>>(srcI, dstI);
    k_gstart<<<1, GG>>>(batch);

    // scale 0: copy x -> h, pool, init logits
    k_pool<false><<<GG, DD>>>(x, fcW, fcb, 1);

    for (int l = 0; l < LL; l++) {
        k_gather<<<(NN * 32 + 255) / 256, 256>>>();
        k_gemm<false><<<NBLK, 256, GEMM_SMEM>>>(cW1 + l * DD * DD, cb1 + l * DD);
        k_stats<<<1, DD>>>(cbng + l * DD, cbnb + l * DD);
        k_gemm<true><<<NBLK, 256, GEMM_SMEM>>>(cW2 + l * DD * DD, cb2 + l * DD);
        k_stats<<<1, DD>>>(bng + l * DD, bnb + l * DD);
        k_pool<true><<<GG, DD>>>(nullptr, fcW + (l + 1) * DD * CC, fcb + (l + 1) * CC, 0);
    }

    k_softmax<<<(GG + 255) / 256, 256>>>(out);
}

// round 4
// speedup vs baseline: 1.2446x; 1.2446x over previous
#include <cuda_runtime.h>
#include <cuda_fp16.h>

// Problem constants (fixed shapes)
#define NN 50000
#define EE 1600000
#define DD 128
#define CC 10
#define LL 4
#define GG 512
#define NBLK 391            // ceil(NN/128)
#define NBP 392             // padded for float4 reduce (pad entry stays 0)
#define BN_EPS 1e-5f
#define SCAN_T 1024
#define SCAN_B 49           // 49*1024 >= 50000

// ---------------- scratch (device globals; no allocations) ----------------
__device__ __half g_hh[NN * DD];      // node features (half) for gather
__device__ float g_z[NN * DD];        // ping (gather out / GEMM2 out)
__device__ float g_y[NN * DD];        // pong (GEMM1 out)
__device__ int   g_rowptr[NN + 1];
__device__ int   g_off[NN];           // counts -> row starts -> fill cursors
__device__ int   g_col[EE];
__device__ int   g_gstart[GG + 1];
__device__ int   g_tmp[SCAN_B * SCAN_T];
__device__ int   g_bsum[SCAN_B];
__device__ int   g_boff[SCAN_B];
__device__ float g_part[256 * NBP];   // transposed BN partials [stat][block]
__device__ float g_scale[DD];
__device__ float g_shift[DD];
__device__ float g_logits[GG * CC];
__device__ int   g_ctr;               // last-block ticket (reset after use)

// ---------------- CSR build ----------------
__global__ void k_zero_off() {
    int i = blockIdx.x * blockDim.x + threadIdx.x;
    if (i < NN) g_off[i] = 0;
}

__global__ void k_hist(const int* __restrict__ dst) {
    int e = blockIdx.x * blockDim.x + threadIdx.x;   // e indexes groups of 4
    if (e * 4 < EE) {
        int4 d = ((const int4*)dst)[e];
        atomicAdd(&g_off[d.x], 1);
        atomicAdd(&g_off[d.y], 1);
        atomicAdd(&g_off[d.z], 1);
        atomicAdd(&g_off[d.w], 1);
    }
}

// phase 1: per-block inclusive scan
__global__ void k_scan1() {
    int t = threadIdx.x, b = blockIdx.x;
    int i = b * SCAN_T + t;
    int v = (i < NN) ? g_off[i] : 0;
    int lane = t & 31, wid = t >> 5;
    int x = v;
#pragma unroll
    for (int o = 1; o < 32; o <<= 1) {
        int y = __shfl_up_sync(~0u, x, o);
        if (lane >= o) x += y;
    }
    __shared__ int ws[32];
    if (lane == 31) ws[wid] = x;
    __syncthreads();
    if (wid == 0) {
        int y = ws[lane];
#pragma unroll
        for (int o = 1; o < 32; o <<= 1) {
            int z = __shfl_up_sync(~0u, y, o);
            if (lane >= o) y += z;
        }
        ws[lane] = y;
    }
    __syncthreads();
    int incl = x + (wid ? ws[wid - 1] : 0);
    g_tmp[b * SCAN_T + t] = incl;
    if (t == SCAN_T - 1) g_bsum[b] = incl;
}

// phase 2: scan block sums (1 block, 512 thr) + graph boundaries
__global__ void k_scan2(const int* __restrict__ batch) {
    int t = threadIdx.x;
    __shared__ int tot0;
    int v = 0;
    if (t < SCAN_B) v = g_bsum[t];
    int x = v;
    if (t < 64) {
        int lane = t & 31;
#pragma unroll
        for (int o = 1; o < 32; o <<= 1) {
            int y = __shfl_up_sync(~0u, x, o);
            if (lane >= o) x += y;
        }
    }
    if (t == 31) tot0 = x;
    __syncthreads();
    if (t >= 32 && t < 64) x += tot0;
    if (t < SCAN_B) g_boff[t] = x - v;   // exclusive
    // graph boundaries (batch sorted): 512 threads
    int g = t;
    int lo = 0, hi = NN;
    while (lo < hi) {
        int mid = (lo + hi) >> 1;
        if (batch[mid] < g) lo = mid + 1; else hi = mid;
    }
    g_gstart[g] = lo;
    if (g == 0) g_gstart[GG] = NN;
}

// phase 3: finalize rowptr + row starts
__global__ void k_scan3() {
    int t = threadIdx.x, b = blockIdx.x;
    int i = b * SCAN_T + t;
    if (i < NN) {
        int incl = g_tmp[b * SCAN_T + t] + g_boff[b];
        int cnt = g_off[i];
        g_rowptr[i + 1] = incl;
        g_off[i] = incl - cnt;
    }
    if (i == 0) g_rowptr[0] = 0;
}

__global__ void k_fill(const int* __restrict__ src, const int* __restrict__ dst) {
    int e = blockIdx.x * blockDim.x + threadIdx.x;
    if (e * 4 < EE) {
        int4 s = ((const int4*)src)[e];
        int4 d = ((const int4*)dst)[e];
        int p;
        p = atomicAdd(&g_off[d.x], 1); g_col[p] = s.x;
        p = atomicAdd(&g_off[d.y], 1); g_col[p] = s.y;
        p = atomicAdd(&g_off[d.z], 1); g_col[p] = s.z;
        p = atomicAdd(&g_off[d.w], 1); g_col[p] = s.w;
    }
}

// ---------------- gather (fp16 src, fp32 acc): z = h + sum h[src] ----------
__device__ __forceinline__ float4 cvt4(uint2 u) {
    __half2 a = *(__half2*)&u.x, b = *(__half2*)&u.y;
    float2 fa = __half22float2(a), fb = __half22float2(b);
    return make_float4(fa.x, fa.y, fb.x, fb.y);
}

__global__ void k_gather() {
    int gw   = (blockIdx.x * blockDim.x + threadIdx.x) >> 5;
    int lane = threadIdx.x & 31;
    if (gw >= NN) return;
    const uint2* hv = (const uint2*)g_hh;   // 32 uint2 per row (4 halves each)
    float4 acc = cvt4(hv[gw * 32 + lane]);
    int i = g_rowptr[gw];
    int e = g_rowptr[gw + 1];
    for (; i + 4 <= e; i += 4) {
        int n0 = g_col[i], n1 = g_col[i + 1], n2 = g_col[i + 2], n3 = g_col[i + 3];
        float4 v0 = cvt4(hv[n0 * 32 + lane]);
        float4 v1 = cvt4(hv[n1 * 32 + lane]);
        float4 v2 = cvt4(hv[n2 * 32 + lane]);
        float4 v3 = cvt4(hv[n3 * 32 + lane]);
        acc.x += (v0.x + v1.x) + (v2.x + v3.x);
        acc.y += (v0.y + v1.y) + (v2.y + v3.y);
        acc.z += (v0.z + v1.z) + (v2.z + v3.z);
        acc.w += (v0.w + v1.w) + (v2.w + v3.w);
    }
    for (; i < e; i++) {
        float4 v = cvt4(hv[g_col[i] * 32 + lane]);
        acc.x += v.x; acc.y += v.y; acc.z += v.z; acc.w += v.w;
    }
    ((float4*)g_z)[gw * 32 + lane] = acc;
}

// ---------------- GEMM: C = act(A) @ W + bias, fused BN stats ----------------
// FUSE=false: A = g_z raw, C = g_y; stats -> scale/shift from (gamma,beta)
// FUSE=true : A = relu(g_y*scale+shift), C = g_z
#define ASTRIDE 132
#define GEMM_SMEM ((128 * ASTRIDE + 128 * 128) * 4)

__device__ __forceinline__ unsigned long long pk2(float a, float b) {
    unsigned long long r;
    asm("mov.b64 %0, {%1, %2};" : "=l"(r) : "r"(__float_as_uint(a)), "r"(__float_as_uint(b)));
    return r;
}

template <bool FUSE>
__global__ __launch_bounds__(256, 1) void k_gemm(const float* __restrict__ W,
                                                 const float* __restrict__ bias,
                                                 const float* __restrict__ gamma,
                                                 const float* __restrict__ beta) {
    extern __shared__ float sm[];
    float* As = sm;                       // [128][ASTRIDE]
    float* Bs = sm + 128 * ASTRIDE;       // [128][128] k-major

    const float* A  = FUSE ? g_y : g_z;
    float*       Cm = FUSE ? g_z : g_y;

    int tid = threadIdx.x;
    int m0  = blockIdx.x << 7;

    // ---- load W tile ----
    {
        const float4* Wv = (const float4*)W;
        float4* Bv = (float4*)Bs;
#pragma unroll
        for (int i = 0; i < 16; i++) Bv[i * 256 + tid] = Wv[i * 256 + tid];
    }
    // ---- load A tile (optionally fused BN+ReLU) ----
    {
        int c4 = tid & 31;   // float4 column, fixed per thread
        int r0 = tid >> 5;
        float4 sc4, sh4;
        if (FUSE) {
            sc4 = ((const float4*)g_scale)[c4];
            sh4 = ((const float4*)g_shift)[c4];
        }
        const float4* Av = (const float4*)A;
#pragma unroll
        for (int i = 0; i < 16; i++) {
            int row = i * 8 + r0;
            int gm  = m0 + row;
            float4 v = make_float4(0.f, 0.f, 0.f, 0.f);
            if (gm < NN) {
                v = Av[gm * 32 + c4];
                if (FUSE) {
                    v.x = fmaxf(fmaf(v.x, sc4.x, sh4.x), 0.f);
                    v.y = fmaxf(fmaf(v.y, sc4.y, sh4.y), 0.f);
                    v.z = fmaxf(fmaf(v.z, sc4.z, sh4.z), 0.f);
                    v.w = fmaxf(fmaf(v.w, sc4.w, sh4.w), 0.f);
                }
            }
            *(float4*)(As + row * ASTRIDE + c4 * 4) = v;
        }
    }
    __syncthreads();

    int tx = tid & 15, ty = tid >> 4;
    unsigned long long acc[8][4];
#pragma unroll
    for (int i = 0; i < 8; i++)
#pragma unroll
        for (int j = 0; j < 4; j++) acc[i][j] = 0ull;

    const float* arow = As + (ty * 8) * ASTRIDE;
    const float* bcol = Bs + tx * 8;

    for (int k4 = 0; k4 < 128; k4 += 4) {
        unsigned long long b2[4][4];
#pragma unroll
        for (int kk = 0; kk < 4; kk++) {
            float4 p = *(const float4*)(bcol + (k4 + kk) * 128);
            float4 q = *(const float4*)(bcol + (k4 + kk) * 128 + 4);
            b2[kk][0] = pk2(p.x, p.y);
            b2[kk][1] = pk2(p.z, p.w);
            b2[kk][2] = pk2(q.x, q.y);
            b2[kk][3] = pk2(q.z, q.w);
        }
#pragma unroll
        for (int i = 0; i < 8; i++) {
            float4 av = *(const float4*)(arow + i * ASTRIDE + k4);
#pragma unroll
            for (int kk = 0; kk < 4; kk++) {
                float asv = (kk == 0) ? av.x : (kk == 1) ? av.y : (kk == 2) ? av.z : av.w;
                unsigned long long a2 = pk2(asv, asv);
#pragma unroll
                for (int j = 0; j < 4; j++)
                    asm("fma.rn.f32x2 %0, %1, %2, %0;" : "+l"(acc[i][j]) : "l"(a2), "l"(b2[kk][j]));
            }
        }
    }

    // ---- epilogue: bias, store, deterministic BN partials ----
    __syncthreads();                 // done reading As/Bs; reuse sm below
    float* Ssum = sm;                // [16][128]
    float* Ssq  = sm + 2048;         // [16][128]

    float csum[8], csq[8];
#pragma unroll
    for (int j = 0; j < 8; j++) { csum[j] = 0.f; csq[j] = 0.f; }
#pragma unroll
    for (int i = 0; i < 8; i++) {
        int gm = m0 + ty * 8 + i;
        if (gm < NN) {
            float2* crow = (float2*)(Cm + gm * 128);
#pragma unroll
            for (int j = 0; j < 4; j++) {
                float vx = __uint_as_float((unsigned)(acc[i][j] & 0xffffffffull));
                float vy = __uint_as_float((unsigned)(acc[i][j] >> 32));
                int c0 = tx * 8 + 2 * j;
                vx += bias[c0]; vy += bias[c0 + 1];
                crow[c0 >> 1] = make_float2(vx, vy);
                csum[2 * j]     += vx; csq[2 * j]     += vx * vx;
                csum[2 * j + 1] += vy; csq[2 * j + 1] += vy * vy;
            }
        }
    }
#pragma unroll
    for (int j = 0; j < 8; j++) {
        Ssum[ty * 128 + tx * 8 + j] = csum[j];
        Ssq [ty * 128 + tx * 8 + j] = csq[j];
    }
    __syncthreads();
    {
        int c = tid & 127;
        const float* Sx = (tid < 128) ? Ssum : Ssq;
        float s = 0.f;
#pragma unroll
        for (int r = 0; r < 16; r++) s += Sx[r * 128 + c];
        g_part[tid * NBP + blockIdx.x] = s;
    }

    // ---- last block reduces stats -> scale/shift ----
    __shared__ int s_last;
    __threadfence();
    if (tid == 0) s_last = (atomicAdd(&g_ctr, 1) == NBLK - 1);
    __syncthreads();
    if (s_last) {
        __threadfence();
        float s2 = 0.f;
        const float4* pp = (const float4*)(g_part + tid * NBP);
#pragma unroll 8
        for (int b = 0; b < NBP / 4; b++) {
            float4 v = pp[b];
            s2 += (v.x + v.y) + (v.z + v.w);
        }
        float* Red = sm;
        __syncthreads();
        Red[tid] = s2;
        __syncthreads();
        if (tid < 128) {
            float m = Red[tid] * (1.0f / NN);
            float q = Red[128 + tid] * (1.0f / NN);
            float var = fmaxf(q - m * m, 0.f);
            float istd = rsqrtf(var + BN_EPS);
            float sc = istd * gamma[tid];
            g_scale[tid] = sc;
            g_shift[tid] = beta[tid] - m * sc;
        }
        if (tid == 0) g_ctr = 0;
    }
}

// ---------------- normalize(+relu) + write h(half) + pool + head -------------
// NORM=false: src = xsrc (raw fp32 input); NORM=true: src = g_z via scale/shift
template <bool NORM, bool WRITEH>
__global__ void k_pool(const float* __restrict__ xsrc, const float* __restrict__ fcW,
                       const float* __restrict__ fcb, int init) {
    __shared__ float pooled[DD];
    int g = blockIdx.x, d = threadIdx.x;  // 512 blocks x 128 threads
    const float* src = NORM ? g_z : xsrc;
    int s = g_gstart[g], e = g_gstart[g + 1];
    float sc = 0.f, sh = 0.f;
    if (NORM) { sc = g_scale[d]; sh = g_shift[d]; }
    float acc = 0.f;
#pragma unroll 4
    for (int n = s; n < e; n++) {
        float v = src[n * DD + d];
        if (NORM) v = fmaxf(fmaf(v, sc, sh), 0.f);
        if (WRITEH) g_hh[n * DD + d] = __float2half(v);
        acc += v;
    }
    pooled[d] = acc;
    __syncthreads();
    if (d < CC) {
        float lg = fcb[d];
#pragma unroll 8
        for (int k = 0; k < DD; k++) lg += pooled[k] * fcW[k * CC + d];
        if (init) g_logits[g * CC + d] = lg;
        else      g_logits[g * CC + d] += lg;
    }
}

// ---------------- log_softmax ----------------
__global__ void k_softmax(float* __restrict__ out) {
    int g = blockIdx.x * blockDim.x + threadIdx.x;
    if (g >= GG) return;
    float v[CC], mx = -1e30f;
#pragma unroll
    for (int c = 0; c < CC; c++) { v[c] = g_logits[g * CC + c]; mx = fmaxf(mx, v[c]); }
    float ssum = 0.f;
#pragma unroll
    for (int c = 0; c < CC; c++) ssum += expf(v[c] - mx);
    float lse = mx + logf(ssum);
#pragma unroll
    for (int c = 0; c < CC; c++) out[g * CC + c] = v[c] - lse;
}

// ---------------- launch ----------------
extern "C" void kernel_launch(void* const* d_in, const int* in_sizes, int n_in,
                              void* d_out, int out_size) {
    const float* x     = (const float*)d_in[0];
    const int*   ei    = (const int*)d_in[1];
    const int*   batch = (const int*)d_in[2];
    const float* cW1  = (const float*)d_in[4];
    const float* cb1  = (const float*)d_in[5];
    const float* cbng = (const float*)d_in[6];
    const float* cbnb = (const float*)d_in[7];
    const float* cW2  = (const float*)d_in[8];
    const float* cb2  = (const float*)d_in[9];
    const float* bng  = (const float*)d_in[10];
    const float* bnb  = (const float*)d_in[11];
    const float* fcW  = (const float*)d_in[12];
    const float* fcb  = (const float*)d_in[13];
    float* out = (float*)d_out;

    cudaFuncSetAttribute(k_gemm<false>, cudaFuncAttributeMaxDynamicSharedMemorySize, GEMM_SMEM);
    cudaFuncSetAttribute(k_gemm<true>,  cudaFuncAttributeMaxDynamicSharedMemorySize, GEMM_SMEM);

    const int* srcI = ei;
    const int* dstI = ei + EE;

    // CSR + graph boundaries
    k_zero_off<<<SCAN_B, SCAN_T>>>();
    k_hist<<<(EE / 4 + 255) / 256, 256>>>(dstI);
    k_scan1<<<SCAN_B, SCAN_T>>>();
    k_scan2<<<1, 512>>>(batch);
    k_scan3<<<SCAN_B, SCAN_T>>>();
    k_fill<<<(EE / 4 + 255) / 256, 256>>>(srcI, dstI);

    // scale 0: pool x, write h(half), init logits
    k_pool<false, true><<<GG, DD>>>(x, fcW, fcb, 1);

    for (int l = 0; l < LL; l++) {
        k_gather<<<(NN * 32 + 255) / 256, 256>>>();
        k_gemm<false><<<NBLK, 256, GEMM_SMEM>>>(cW1 + l * DD * DD, cb1 + l * DD,
                                                cbng + l * DD, cbnb + l * DD);
        k_gemm<true><<<NBLK, 256, GEMM_SMEM>>>(cW2 + l * DD * DD, cb2 + l * DD,
                                               bng + l * DD, bnb + l * DD);
        if (l < LL - 1)
            k_pool<true, true><<<GG, DD>>>(nullptr, fcW + (l + 1) * DD * CC,
                                           fcb + (l + 1) * CC, 0);
        else
            k_pool<true, false><<<GG, DD>>>(nullptr, fcW + (l + 1) * DD * CC,
                                            fcb + (l + 1) * CC, 0);
    }

    k_softmax<<<(GG + 255) / 256, 256>>>(out);
}

// round 6
// speedup vs baseline: 1.9789x; 1.5900x over previous
#include <cuda_runtime.h>
#include <cuda_fp16.h>

// Problem constants (fixed shapes)
#define NN 50000
#define EE 1600000
#define DD 128
#define CC 10
#define LL 4
#define GG 512
#define NBLK 391            // ceil(NN/128)
#define NBP 392             // padded for float4 reduce (pad entry stays 0)
#define BN_EPS 1e-5f
#define SCAN_T 1024
#define SCAN_B 49           // 49*1024 >= 50000
#define BST 136             // smem tile stride in halves (272B rows: 16B-aligned, 4-bank shift)

// ---------------- scratch (device globals; no allocations) ----------------
__device__ __half g_hh[NN * DD];      // node features (half) for gather
__device__ __half g_zh[NN * DD];      // gather out (half) = GEMM1 A operand
__device__ float g_y[NN * DD];        // GEMM1 out (fp32)
__device__ float g_z[NN * DD];        // GEMM2 out (fp32)
__device__ int   g_rowptr[NN + 1];
__device__ int   g_off[NN];
__device__ int   g_col[EE];
__device__ int   g_gstart[GG + 1];
__device__ int   g_tmp[SCAN_B * SCAN_T];
__device__ int   g_bsum[SCAN_B];
__device__ int   g_boff[SCAN_B];
__device__ float g_part[256 * NBP];   // transposed BN partials [stat][block]
__device__ float g_scale[DD];
__device__ float g_shift[DD];
__device__ float g_logits[GG * CC];
__device__ int   g_ctr;

// ---------------- CSR build ----------------
__global__ void k_zero_off() {
    int i = blockIdx.x * blockDim.x + threadIdx.x;
    if (i < NN) g_off[i] = 0;
}

__global__ void k_hist(const int* __restrict__ dst) {
    int e = blockIdx.x * blockDim.x + threadIdx.x;
    if (e * 4 < EE) {
        int4 d = ((const int4*)dst)[e];
        atomicAdd(&g_off[d.x], 1);
        atomicAdd(&g_off[d.y], 1);
        atomicAdd(&g_off[d.z], 1);
        atomicAdd(&g_off[d.w], 1);
    }
}

__global__ void k_scan1() {
    int t = threadIdx.x, b = blockIdx.x;
    int i = b * SCAN_T + t;
    int v = (i < NN) ? g_off[i] : 0;
    int lane = t & 31, wid = t >> 5;
    int x = v;
#pragma unroll
    for (int o = 1; o < 32; o <<= 1) {
        int y = __shfl_up_sync(~0u, x, o);
        if (lane >= o) x += y;
    }
    __shared__ int ws[32];
    if (lane == 31) ws[wid] = x;
    __syncthreads();
    if (wid == 0) {
        int y = ws[lane];
#pragma unroll
        for (int o = 1; o < 32; o <<= 1) {
            int z = __shfl_up_sync(~0u, y, o);
            if (lane >= o) y += z;
        }
        ws[lane] = y;
    }
    __syncthreads();
    int incl = x + (wid ? ws[wid - 1] : 0);
    g_tmp[b * SCAN_T + t] = incl;
    if (t == SCAN_T - 1) g_bsum[b] = incl;
}

__global__ void k_scan2(const int* __restrict__ batch) {
    int t = threadIdx.x;
    __shared__ int tot0;
    int v = 0;
    if (t < SCAN_B) v = g_bsum[t];
    int x = v;
    if (t < 64) {
        int lane = t & 31;
#pragma unroll
        for (int o = 1; o < 32; o <<= 1) {
            int y = __shfl_up_sync(~0u, x, o);
            if (lane >= o) x += y;
        }
    }
    if (t == 31) tot0 = x;
    __syncthreads();
    if (t >= 32 && t < 64) x += tot0;
    if (t < SCAN_B) g_boff[t] = x - v;
    int g = t;
    int lo = 0, hi = NN;
    while (lo < hi) {
        int mid = (lo + hi) >> 1;
        if (batch[mid] < g) lo = mid + 1; else hi = mid;
    }
    g_gstart[g] = lo;
    if (g == 0) g_gstart[GG] = NN;
}

__global__ void k_scan3() {
    int t = threadIdx.x, b = blockIdx.x;
    int i = b * SCAN_T + t;
    if (i < NN) {
        int incl = g_tmp[b * SCAN_T + t] + g_boff[b];
        int cnt = g_off[i];
        g_rowptr[i + 1] = incl;
        g_off[i] = incl - cnt;
    }
    if (i == 0) g_rowptr[0] = 0;
}

__global__ void k_fill(const int* __restrict__ src, const int* __restrict__ dst) {
    int e = blockIdx.x * blockDim.x + threadIdx.x;
    if (e * 4 < EE) {
        int4 s = ((const int4*)src)[e];
        int4 d = ((const int4*)dst)[e];
        int p;
        p = atomicAdd(&g_off[d.x], 1); g_col[p] = s.x;
        p = atomicAdd(&g_off[d.y], 1); g_col[p] = s.y;
        p = atomicAdd(&g_off[d.z], 1); g_col[p] = s.z;
        p = atomicAdd(&g_off[d.w], 1); g_col[p] = s.w;
    }
}

// ---------------- gather (fp16 src, fp32 acc, fp16 out) ----------------
__device__ __forceinline__ float4 cvt4(uint2 u) {
    __half2 a = *(__half2*)&u.x, b = *(__half2*)&u.y;
    float2 fa = __half22float2(a), fb = __half22float2(b);
    return make_float4(fa.x, fa.y, fb.x, fb.y);
}

__global__ void k_gather() {
    int gw   = (blockIdx.x * blockDim.x + threadIdx.x) >> 5;
    int lane = threadIdx.x & 31;
    if (gw >= NN) return;
    const uint2* hv = (const uint2*)g_hh;
    float4 acc = cvt4(hv[gw * 32 + lane]);
    int i = g_rowptr[gw];
    int e = g_rowptr[gw + 1];
    for (; i + 4 <= e; i += 4) {
        int n0 = g_col[i], n1 = g_col[i + 1], n2 = g_col[i + 2], n3 = g_col[i + 3];
        float4 v0 = cvt4(hv[n0 * 32 + lane]);
        float4 v1 = cvt4(hv[n1 * 32 + lane]);
        float4 v2 = cvt4(hv[n2 * 32 + lane]);
        float4 v3 = cvt4(hv[n3 * 32 + lane]);
        acc.x += (v0.x + v1.x) + (v2.x + v3.x);
        acc.y += (v0.y + v1.y) + (v2.y + v3.y);
        acc.z += (v0.z + v1.z) + (v2.z + v3.z);
        acc.w += (v0.w + v1.w) + (v2.w + v3.w);
    }
    for (; i < e; i++) {
        float4 v = cvt4(hv[g_col[i] * 32 + lane]);
        acc.x += v.x; acc.y += v.y; acc.z += v.z; acc.w += v.w;
    }
    __half2 h0 = __floats2half2_rn(acc.x, acc.y);
    __half2 h1 = __floats2half2_rn(acc.z, acc.w);
    uint2 st;
    st.x = *(unsigned*)&h0; st.y = *(unsigned*)&h1;
    ((uint2*)g_zh)[gw * 32 + lane] = st;
}

// ---------------- HMMA GEMM: C = act(A) @ W + bias, fused BN stats ----------
// FUSE=false: A = g_zh (half), C = g_y
// FUSE=true : A = relu(g_y*scale+shift) (->half), C = g_z
#define GEMM_SMEM (2 * 128 * BST * 2)   // As + Bs, half

#define LDSM_X4(r0, r1, r2, r3, addr) \
    asm volatile("ldmatrix.sync.aligned.m8n8.x4.shared.b16 {%0,%1,%2,%3},[%4];" \
                 : "=r"(r0), "=r"(r1), "=r"(r2), "=r"(r3) : "r"(addr))
#define LDSM_X4T(r0, r1, r2, r3, addr) \
    asm volatile("ldmatrix.sync.aligned.m8n8.x4.trans.shared.b16 {%0,%1,%2,%3},[%4];" \
                 : "=r"(r0), "=r"(r1), "=r"(r2), "=r"(r3) : "r"(addr))
#define MMA16816(c, a, b) \
    asm volatile("mma.sync.aligned.m16n8k16.row.col.f32.f16.f16.f32 " \
                 "{%0,%1,%2,%3},{%4,%5,%6,%7},{%8,%9},{%0,%1,%2,%3};" \
                 : "+f"(c[0]), "+f"(c[1]), "+f"(c[2]), "+f"(c[3]) \
                 : "r"(a[0]), "r"(a[1]), "r"(a[2]), "r"(a[3]), "r"(b[0]), "r"(b[1]))

template <bool FUSE>
__global__ __launch_bounds__(256, 2) void k_gemm(const float* __restrict__ W,
                                                 const float* __restrict__ bias,
                                                 const float* __restrict__ gamma,
                                                 const float* __restrict__ beta) {
    extern __shared__ char smraw[];
    __half* As = (__half*)smraw;             // [128][BST]
    __half* Bs = As + 128 * BST;             // [128][BST] k-major (row=k)
    float*  Cm = FUSE ? g_z : g_y;

    int tid = threadIdx.x;
    int m0  = blockIdx.x << 7;

    // ---- load W tile -> Bs (k-major, fp32 -> half) ----
    {
        const float4* Wv = (const float4*)W;
#pragma unroll
        for (int it = 0; it < 16; it++) {
            int idx = it * 256 + tid;
            int k = idx >> 5, nq = idx & 31;
            float4 w = Wv[idx];
            __half2 h0 = __floats2half2_rn(w.x, w.y);
            __half2 h1 = __floats2half2_rn(w.z, w.w);
            uint2 st; st.x = *(unsigned*)&h0; st.y = *(unsigned*)&h1;
            *(uint2*)(Bs + k * BST + nq * 4) = st;
        }
    }
    // ---- load A tile -> As ----
    if (!FUSE) {
        const uint4* Av = (const uint4*)g_zh;   // 16 uint4 per row
#pragma unroll
        for (int it = 0; it < 8; it++) {
            int idx = it * 256 + tid;
            int row = idx >> 4, c8 = idx & 15;
            uint4 v = make_uint4(0u, 0u, 0u, 0u);
            if (m0 + row < NN) v = Av[(m0 + row) * 16 + c8];
            *(uint4*)(As + row * BST + c8 * 8) = v;
        }
    } else {
        int c4 = tid & 31;
        float4 sc4 = ((const float4*)g_scale)[c4];
        float4 sh4 = ((const float4*)g_shift)[c4];
        const float4* Av = (const float4*)g_y;
#pragma unroll
        for (int it = 0; it < 16; it++) {
            int idx = it * 256 + tid;
            int row = idx >> 5;
            float4 v = make_float4(0.f, 0.f, 0.f, 0.f);
            if (m0 + row < NN) {
                v = Av[(m0 + row) * 32 + c4];
                v.x = fmaxf(fmaf(v.x, sc4.x, sh4.x), 0.f);
                v.y = fmaxf(fmaf(v.y, sc4.y, sh4.y), 0.f);
                v.z = fmaxf(fmaf(v.z, sc4.z, sh4.z), 0.f);
                v.w = fmaxf(fmaf(v.w, sc4.w, sh4.w), 0.f);
            }
            __half2 h0 = __floats2half2_rn(v.x, v.y);
            __half2 h1 = __floats2half2_rn(v.z, v.w);
            uint2 st; st.x = *(unsigned*)&h0; st.y = *(unsigned*)&h1;
            *(uint2*)(As + row * BST + c4 * 4) = st;
        }
    }
    __syncthreads();

    // ---- mainloop ----
    int warp = tid >> 5, lane = tid & 31;
    int wm = warp & 3, wn = warp >> 2;       // warp tile: rows wm*32, cols wn*64
    int l15 = lane & 15, lhi8 = (lane & 16) >> 1;   // 0 or 8

    float acc[2][8][4];
#pragma unroll
    for (int i = 0; i < 2; i++)
#pragma unroll
        for (int j = 0; j < 8; j++)
#pragma unroll
            for (int q = 0; q < 4; q++) acc[i][j][q] = 0.f;

    unsigned asb = (unsigned)__cvta_generic_to_shared(As);
    unsigned bsb = (unsigned)__cvta_generic_to_shared(Bs);
    // A addr: row = wm*32 + ma*16 + l15, col = k0 + lhi8
    unsigned aaddr0 = asb + ((wm * 32 + l15) * BST + lhi8) * 2;
    // B addr: row = k0 + l15, col = wn*64 + p*16 + lhi8
    unsigned baddr0 = bsb + (l15 * BST + wn * 64 + lhi8) * 2;

#pragma unroll
    for (int k0 = 0; k0 < 128; k0 += 16) {
        unsigned a[2][4], b[8][4];
        LDSM_X4(a[0][0], a[0][1], a[0][2], a[0][3], aaddr0 + k0 * 2);
        LDSM_X4(a[1][0], a[1][1], a[1][2], a[1][3], aaddr0 + (16 * BST + k0) * 2);
#pragma unroll
        for (int p = 0; p < 4; p++) {
            unsigned ba = baddr0 + (k0 * BST + p * 16) * 2;
            LDSM_X4T(b[2 * p][0], b[2 * p][1], b[2 * p + 1][0], b[2 * p + 1][1], ba);
        }
#pragma unroll
        for (int ma = 0; ma < 2; ma++)
#pragma unroll
            for (int na = 0; na < 8; na++)
                MMA16816(acc[ma][na], a[ma], b[na]);
    }

    // ---- epilogue: bias, store C, deterministic BN partials ----
    __syncthreads();
    float* Ssum = (float*)smraw;         // [32][128]
    float* Ssq  = Ssum + 32 * 128;       // [32][128]

    int g4 = lane >> 2, t4 = lane & 3;
    int slot = wm * 8 + g4;
#pragma unroll
    for (int na = 0; na < 8; na++) {
        int col = wn * 64 + na * 8 + t4 * 2;
        float2 b2 = *(const float2*)(bias + col);
        float s0 = 0.f, s1 = 0.f, q0 = 0.f, q1 = 0.f;
#pragma unroll
        for (int ma = 0; ma < 2; ma++) {
            int m = m0 + wm * 32 + ma * 16 + g4;
            float v0 = acc[ma][na][0] + b2.x;
            float v1 = acc[ma][na][1] + b2.y;
            if (m < NN) {
                *(float2*)(Cm + m * 128 + col) = make_float2(v0, v1);
                s0 += v0; q0 += v0 * v0; s1 += v1; q1 += v1 * v1;
            }
            int m2 = m + 8;
            v0 = acc[ma][na][2] + b2.x;
            v1 = acc[ma][na][3] + b2.y;
            if (m2 < NN) {
                *(float2*)(Cm + m2 * 128 + col) = make_float2(v0, v1);
                s0 += v0; q0 += v0 * v0; s1 += v1; q1 += v1 * v1;
            }
        }
        Ssum[slot * 128 + col] = s0; Ssum[slot * 128 + col + 1] = s1;
        Ssq [slot * 128 + col] = q0; Ssq [slot * 128 + col + 1] = q1;
    }
    __syncthreads();
    {
        int c = tid & 127;
        const float* Sx = (tid < 128) ? Ssum : Ssq;
        float s = 0.f;
#pragma unroll
        for (int r = 0; r < 32; r++) s += Sx[r * 128 + c];
        g_part[tid * NBP + blockIdx.x] = s;
    }

    // ---- last block reduces stats -> scale/shift ----
    __shared__ int s_last;
    __threadfence();
    if (tid == 0) s_last = (atomicAdd(&g_ctr, 1) == NBLK - 1);
    __syncthreads();
    if (s_last) {
        __threadfence();
        float s2 = 0.f;
        const float4* pp = (const float4*)(g_part + tid * NBP);
#pragma unroll 8
        for (int b = 0; b < NBP / 4; b++) {
            float4 v = pp[b];
            s2 += (v.x + v.y) + (v.z + v.w);
        }
        float* Red = (float*)smraw;
        __syncthreads();
        Red[tid] = s2;
        __syncthreads();
        if (tid < 128) {
            float m = Red[tid] * (1.0f / NN);
            float q = Red[128 + tid] * (1.0f / NN);
            float var = fmaxf(q - m * m, 0.f);
            float istd = rsqrtf(var + BN_EPS);
            float sc = istd * gamma[tid];
            g_scale[tid] = sc;
            g_shift[tid] = beta[tid] - m * sc;
        }
        if (tid == 0) g_ctr = 0;
    }
}

// ---------------- normalize(+relu) + write h(half) + pool + head -------------
template <bool NORM, bool WRITEH>
__global__ void k_pool(const float* __restrict__ xsrc, const float* __restrict__ fcW,
                       const float* __restrict__ fcb, int init) {
    __shared__ float pooled[DD];
    int g = blockIdx.x, d = threadIdx.x;
    const float* src = NORM ? g_z : xsrc;
    int s = g_gstart[g], e = g_gstart[g + 1];
    float sc = 0.f, sh = 0.f;
    if (NORM) { sc = g_scale[d]; sh = g_shift[d]; }
    float acc = 0.f;
#pragma unroll 4
    for (int n = s; n < e; n++) {
        float v = src[n * DD + d];
        if (NORM) v = fmaxf(fmaf(v, sc, sh), 0.f);
        if (WRITEH) g_hh[n * DD + d] = __float2half(v);
        acc += v;
    }
    pooled[d] = acc;
    __syncthreads();
    if (d < CC) {
        float lg = fcb[d];
#pragma unroll 8
        for (int k = 0; k < DD; k++) lg += pooled[k] * fcW[k * CC + d];
        if (init) g_logits[g * CC + d] = lg;
        else      g_logits[g * CC + d] += lg;
    }
}

// ---------------- log_softmax ----------------
__global__ void k_softmax(float* __restrict__ out) {
    int g = blockIdx.x * blockDim.x + threadIdx.x;
    if (g >= GG) return;
    float v[CC], mx = -1e30f;
#pragma unroll
    for (int c = 0; c < CC; c++) { v[c] = g_logits[g * CC + c]; mx = fmaxf(mx, v[c]); }
    float ssum = 0.f;
#pragma unroll
    for (int c = 0; c < CC; c++) ssum += expf(v[c] - mx);
    float lse = mx + logf(ssum);
#pragma unroll
    for (int c = 0; c < CC; c++) out[g * CC + c] = v[c] - lse;
}

// ---------------- launch ----------------
extern "C" void kernel_launch(void* const* d_in, const int* in_sizes, int n_in,
                              void* d_out, int out_size) {
    const float* x     = (const float*)d_in[0];
    const int*   ei    = (const int*)d_in[1];
    const int*   batch = (const int*)d_in[2];
    const float* cW1  = (const float*)d_in[4];
    const float* cb1  = (const float*)d_in[5];
    const float* cbng = (const float*)d_in[6];
    const float* cbnb = (const float*)d_in[7];
    const float* cW2  = (const float*)d_in[8];
    const float* cb2  = (const float*)d_in[9];
    const float* bng  = (const float*)d_in[10];
    const float* bnb  = (const float*)d_in[11];
    const float* fcW  = (const float*)d_in[12];
    const float* fcb  = (const float*)d_in[13];
    float* out = (float*)d_out;

    cudaFuncSetAttribute(k_gemm<false>, cudaFuncAttributeMaxDynamicSharedMemorySize, GEMM_SMEM);
    cudaFuncSetAttribute(k_gemm<true>,  cudaFuncAttributeMaxDynamicSharedMemorySize, GEMM_SMEM);

    const int* srcI = ei;
    const int* dstI = ei + EE;

    k_zero_off<<<SCAN_B, SCAN_T>>>();
    k_hist<<<(EE / 4 + 255) / 256, 256>>>(dstI);
    k_scan1<<<SCAN_B, SCAN_T>>>();
    k_scan2<<<1, 512>>>(batch);
    k_scan3<<<SCAN_B, SCAN_T>>>();
    k_fill<<<(EE / 4 + 255) / 256, 256>>>(srcI, dstI);

    k_pool<false, true><<<GG, DD>>>(x, fcW, fcb, 1);

    for (int l = 0; l < LL; l++) {
        k_gather<<<(NN * 32 + 255) / 256, 256>>>();
        k_gemm<false><<<NBLK, 256, GEMM_SMEM>>>(cW1 + l * DD * DD, cb1 + l * DD,
                                                cbng + l * DD, cbnb + l * DD);
        k_gemm<true><<<NBLK, 256, GEMM_SMEM>>>(cW2 + l * DD * DD, cb2 + l * DD,
                                               bng + l * DD, bnb + l * DD);
        if (l < LL - 1)
            k_pool<true, true><<<GG, DD>>>(nullptr, fcW + (l + 1) * DD * CC,
                                           fcb + (l + 1) * CC, 0);
        else
            k_pool<true, false><<<GG, DD>>>(nullptr, fcW + (l + 1) * DD * CC,
                                            fcb + (l + 1) * CC, 0);
    }

    k_softmax<<<(GG + 255) / 256, 256>>>(out);
}